// round 8
// baseline (speedup 1.0000x reference)
#include <cuda_runtime.h>
#include <math.h>

#define N_NODES 100000
#define N_EDGES 1600000
#define D 128
#define NEG_SLOPE 0.2f
#define LN_EPS 1e-5f
#define TOT_EDGES (N_EDGES + N_NODES)
#define SCAN_B 1024
#define SCAN_NB ((N_NODES + SCAN_B - 1) / SCAN_B)   // 98

typedef unsigned long long ull;

// ---------------- device scratch (static; no allocation allowed) ----------------
static __device__ int   g_is64;
static __device__ int   g_deg[N_NODES];
static __device__ float g_wsum[N_NODES];
static __device__ int   g_rowptr[N_NODES + 1];
static __device__ int   g_cursor[N_NODES];
static __device__ int   g_bsum[SCAN_NB];
static __device__ int   g_boff[SCAN_NB];
static __device__ int   g_csr_src[TOT_EDGES];
static __device__ float g_csr_ew[TOT_EDGES];
static __device__ __align__(16) float g_h[(size_t)N_NODES * D];  // transformed features
static __device__ __align__(16) float g_a[(size_t)N_NODES * D];  // layer activations
static __device__ float g_alpha_s[N_NODES];
static __device__ float g_alpha_d[N_NODES];
static __device__ float g_ce[2];

// ---------------- helpers ----------------
__device__ __forceinline__ float gelu_exact(float v) {
    return 0.5f * v * (1.0f + erff(v * 0.7071067811865475f));
}
__device__ __forceinline__ float lrelu(float v) {
    return v > 0.0f ? v : NEG_SLOPE * v;
}
__device__ __forceinline__ void edge_sd(const void* ei, int e, int& s, int& d) {
    if (g_is64) {
        const long long* p = (const long long*)ei;
        s = (int)p[e];
        d = (int)p[N_EDGES + e];
    } else {
        const int* p = (const int*)ei;
        s = p[e];
        d = p[N_EDGES + e];
    }
}
// packed f32x2 FMA (Blackwell FFMA2; only reachable via explicit PTX)
__device__ __forceinline__ ull ffma2(ull a, ull b, ull c) {
    ull d;
    asm("fma.rn.f32x2 %0, %1, %2, %3;" : "=l"(d) : "l"(a), "l"(b), "l"(c));
    return d;
}
__device__ __forceinline__ ull dup2(float v) {
    ull d;
    unsigned int u = __float_as_uint(v);
    asm("mov.b64 %0, {%1, %1};" : "=l"(d) : "r"(u));
    return d;
}
__device__ __forceinline__ void unpack2(ull v, float& lo, float& hi) {
    unsigned int a, b;
    asm("mov.b64 {%0, %1}, %2;" : "=r"(a), "=r"(b) : "l"(v));
    lo = __uint_as_float(a);
    hi = __uint_as_float(b);
}

// ---------------- dtype detection ----------------
__global__ void k_detect(const int* __restrict__ ei32) {
    int lane = threadIdx.x;
    int orv = 0;
    for (int i = lane; i < 1024; i += 32) orv |= ei32[2 * i + 1];
    #pragma unroll
    for (int o = 16; o; o >>= 1) orv |= __shfl_xor_sync(0xffffffffu, orv, o);
    if (lane == 0) g_is64 = (orv == 0) ? 1 : 0;
}

// ---------------- graph prep ----------------
__global__ void k_init() {
    int i = blockIdx.x * blockDim.x + threadIdx.x;
    if (i < N_NODES) { g_deg[i] = 0; g_wsum[i] = 0.0f; g_cursor[i] = 0; }
}

__global__ void k_hist(const void* __restrict__ ei, const float* __restrict__ ew) {
    int e = blockIdx.x * blockDim.x + threadIdx.x;
    if (e < N_EDGES) {
        int s, d;
        edge_sd(ei, e, s, d);
        atomicAdd(&g_deg[d], 1);
        atomicAdd(&g_wsum[d], ew[e]);
    }
}

// ---- 3-phase multi-block exclusive scan of (deg[i]+1) -> rowptr ----
__global__ void __launch_bounds__(SCAN_B) k_scanA() {
    __shared__ int wsum[32];
    int tid = threadIdx.x, lane = tid & 31, wid = tid >> 5;
    int i = blockIdx.x * SCAN_B + tid;
    int v = (i < N_NODES) ? (g_deg[i] + 1) : 0;
    #pragma unroll
    for (int o = 16; o; o >>= 1) v += __shfl_xor_sync(0xffffffffu, v, o);
    if (lane == 0) wsum[wid] = v;
    __syncthreads();
    if (wid == 0) {
        int w = wsum[lane];
        #pragma unroll
        for (int o = 16; o; o >>= 1) w += __shfl_xor_sync(0xffffffffu, w, o);
        if (lane == 0) g_bsum[blockIdx.x] = w;
    }
}

__global__ void k_scanB() {
    __shared__ int wsum[4];
    int tid = threadIdx.x, lane = tid & 31, wid = tid >> 5;
    int v = (tid < SCAN_NB) ? g_bsum[tid] : 0;
    int x = v;
    #pragma unroll
    for (int o = 1; o < 32; o <<= 1) {
        int y = __shfl_up_sync(0xffffffffu, x, o);
        if (lane >= o) x += y;
    }
    if (lane == 31) wsum[wid] = x;
    __syncthreads();
    int base = 0;
    for (int w = 0; w < wid; w++) base += wsum[w];
    if (tid < SCAN_NB) g_boff[tid] = base + x - v;   // exclusive
}

__global__ void __launch_bounds__(SCAN_B) k_scanC() {
    __shared__ int wsum[32];
    int tid = threadIdx.x, lane = tid & 31, wid = tid >> 5;
    int i = blockIdx.x * SCAN_B + tid;
    int v = (i < N_NODES) ? (g_deg[i] + 1) : 0;
    int x = v;
    #pragma unroll
    for (int o = 1; o < 32; o <<= 1) {
        int y = __shfl_up_sync(0xffffffffu, x, o);
        if (lane >= o) x += y;
    }
    if (lane == 31) wsum[wid] = x;
    __syncthreads();
    if (wid == 0) {
        int w = wsum[lane];
        #pragma unroll
        for (int o = 1; o < 32; o <<= 1) {
            int y = __shfl_up_sync(0xffffffffu, w, o);
            if (lane >= o) w += y;
        }
        wsum[lane] = w;
    }
    __syncthreads();
    int incl = x + (wid > 0 ? wsum[wid - 1] : 0) + g_boff[blockIdx.x];
    if (i < N_NODES) g_rowptr[i + 1] = incl;
    if (i == 0) g_rowptr[0] = 0;
}

__global__ void k_scatter(const void* __restrict__ ei, const float* __restrict__ ew) {
    int e = blockIdx.x * blockDim.x + threadIdx.x;
    if (e < N_EDGES) {
        int s, d;
        edge_sd(ei, e, s, d);
        int pos = g_rowptr[d] + atomicAdd(&g_cursor[d], 1);
        g_csr_src[pos] = s;
        g_csr_ew[pos]  = ew[e];
    }
}

__global__ void k_selfloop() {
    int n = blockIdx.x * blockDim.x + threadIdx.x;
    if (n < N_NODES) {
        int pos = g_rowptr[n + 1] - 1;
        g_csr_src[pos] = n;
        int dg = g_deg[n];
        g_csr_ew[pos] = g_wsum[n] / (float)(dg > 0 ? dg : 1);
    }
}

__global__ void k_pre(const float* __restrict__ lew, const float* __restrict__ aedge) {
    int l = blockIdx.x;
    int t = threadIdx.x;
    __shared__ float red[4];
    float p = lew[l * D + t] * aedge[l * D + t];
    #pragma unroll
    for (int o = 16; o; o >>= 1) p += __shfl_xor_sync(0xffffffffu, p, o);
    if ((t & 31) == 0) red[t >> 5] = p;
    __syncthreads();
    if (t == 0) g_ce[l] = red[0] + red[1] + red[2] + red[3];
}

// ---------------- GEMM (FFMA2) + fused alpha epilogue ----------------
// g_h[N,128] = X @ W. 128 rows/block, 256 threads, 8x8 micro-tile via
// packed fma.rn.f32x2 (acc packs column pairs). K chunked by 32.
#define BK 32
__global__ void __launch_bounds__(256) k_gemm(const float* __restrict__ Xin,
                                              int use_ga,
                                              const float* __restrict__ Wm,
                                              const float* __restrict__ asrc_l,
                                              const float* __restrict__ adst_l) {
    __shared__ float xs[128 * BK];     // [128][32] 16 KB
    __shared__ float ws[BK * 128];     // [32][128] 16 KB
    int tid = threadIdx.x;
    int row0 = blockIdx.x * 128;
    const float* X = use_ga ? g_a : Xin;

    int cg = tid & 15;                 // col group: cols cg*8 .. cg*8+7
    int rg = tid >> 4;                 // row group: rows rg*8 .. rg*8+7
    int lane = tid & 31;

    ull acc[8][4];                     // [row][colpair] packed f32x2
    #pragma unroll
    for (int i = 0; i < 8; i++)
        #pragma unroll
        for (int j = 0; j < 4; j++) acc[i][j] = 0ULL;

    const float4* X4 = (const float4*)X;
    const float4* W4 = (const float4*)Wm;
    float4* xs4 = (float4*)xs;
    float4* ws4 = (float4*)ws;

    for (int kb = 0; kb < 128 / BK; kb++) {
        // load W chunk [BK][128]: 1024 float4s, 4/thread
        #pragma unroll
        for (int j = 0; j < 4; j++) {
            int idx = tid + j * 256;
            int kk = idx >> 5;
            int c  = idx & 31;
            ws4[idx] = W4[(size_t)(kb * BK + kk) * 32 + c];
        }
        // load X chunk [128][BK]: 1024 float4s, 4/thread
        #pragma unroll
        for (int j = 0; j < 4; j++) {
            int idx = tid + j * 256;
            int r = idx >> 3;
            int c = idx & 7;
            int gr = row0 + r;
            float4 v = make_float4(0.f, 0.f, 0.f, 0.f);
            if (gr < N_NODES) v = X4[(size_t)gr * 32 + kb * 8 + c];
            xs4[idx] = v;
        }
        __syncthreads();

        #pragma unroll
        for (int k = 0; k < BK; k++) {
            // b: cols cg*8..+7 as 4 packed pairs (contiguous -> natural packing)
            ulonglong2 b03 = *(const ulonglong2*)&ws[k * 128 + cg * 8];
            ulonglong2 b47 = *(const ulonglong2*)&ws[k * 128 + cg * 8 + 4];
            #pragma unroll
            for (int i = 0; i < 8; i++) {
                ull aa = dup2(xs[(rg * 8 + i) * BK + k]);
                acc[i][0] = ffma2(aa, b03.x, acc[i][0]);
                acc[i][1] = ffma2(aa, b03.y, acc[i][1]);
                acc[i][2] = ffma2(aa, b47.x, acc[i][2]);
                acc[i][3] = ffma2(aa, b47.y, acc[i][3]);
            }
        }
        __syncthreads();
    }

    // epilogue: store H rows + fused alpha dots (16-lane butterfly per row group)
    float4 sA = ((const float4*)asrc_l)[cg * 2];
    float4 sB = ((const float4*)asrc_l)[cg * 2 + 1];
    float4 dA = ((const float4*)adst_l)[cg * 2];
    float4 dB = ((const float4*)adst_l)[cg * 2 + 1];

    #pragma unroll
    for (int i = 0; i < 8; i++) {
        int gr = row0 + rg * 8 + i;
        float v0, v1, v2, v3, v4, v5, v6, v7;
        unpack2(acc[i][0], v0, v1);
        unpack2(acc[i][1], v2, v3);
        unpack2(acc[i][2], v4, v5);
        unpack2(acc[i][3], v6, v7);

        float ss = v0 * sA.x + v1 * sA.y + v2 * sA.z + v3 * sA.w
                 + v4 * sB.x + v5 * sB.y + v6 * sB.z + v7 * sB.w;
        float dd = v0 * dA.x + v1 * dA.y + v2 * dA.z + v3 * dA.w
                 + v4 * dB.x + v5 * dB.y + v6 * dB.z + v7 * dB.w;
        #pragma unroll
        for (int o = 8; o; o >>= 1) {
            ss += __shfl_xor_sync(0xffffffffu, ss, o);
            dd += __shfl_xor_sync(0xffffffffu, dd, o);
        }

        if (gr < N_NODES) {
            float* hp = &g_h[(size_t)gr * D + cg * 8];
            *((float4*)hp)       = make_float4(v0, v1, v2, v3);
            *((float4*)(hp + 4)) = make_float4(v4, v5, v6, v7);
            if (cg == 0) { g_alpha_s[gr] = ss; g_alpha_d[gr] = dd; }
        }
        (void)lane;
    }
}

// softmax-weighted aggregation + bias + GELU; one warp per destination node.
// If is_final: fuse residual + LayerNorm and write to out; else write to g_a.
__global__ void __launch_bounds__(256) k_agg(int l, const float* __restrict__ bias_l,
                                             int is_final,
                                             const float* __restrict__ X,
                                             const float* __restrict__ gamma,
                                             const float* __restrict__ beta,
                                             float* __restrict__ out) {
    int warp = (blockIdx.x * 256 + threadIdx.x) >> 5;
    int lane = threadIdx.x & 31;
    if (warp >= N_NODES) return;
    int n = warp;
    int start = g_rowptr[n], end = g_rowptr[n + 1];
    float ad = g_alpha_d[n];
    float ce = g_ce[l];

    // pass 1: online max + sum-exp
    float m = -1e30f, z = 0.f;
    for (int e = start + lane; e < end; e += 32) {
        int s = g_csr_src[e];
        float lg = lrelu(g_alpha_s[s] + ad + ce * g_csr_ew[e]);
        if (lg > m) { z = z * __expf(m - lg) + 1.0f; m = lg; }
        else        { z += __expf(lg - m); }
    }
    #pragma unroll
    for (int o = 16; o; o >>= 1) {
        float mo = __shfl_xor_sync(0xffffffffu, m, o);
        float zo = __shfl_xor_sync(0xffffffffu, z, o);
        float mn = fmaxf(m, mo);
        z = z * __expf(m - mn) + zo * __expf(mo - mn);
        m = mn;
    }
    float inv_z = 1.0f / z;

    // pass 2: 4-way unrolled warp-wide float4 gather
    float4 acc = make_float4(0.f, 0.f, 0.f, 0.f);
    const float4* h4 = (const float4*)g_h;
    int e = start;
    for (; e + 4 <= end; e += 4) {
        int s0 = g_csr_src[e],     s1 = g_csr_src[e + 1];
        int s2 = g_csr_src[e + 2], s3 = g_csr_src[e + 3];
        float w0 = g_csr_ew[e],     w1 = g_csr_ew[e + 1];
        float w2 = g_csr_ew[e + 2], w3 = g_csr_ew[e + 3];
        float4 h0 = h4[(size_t)s0 * 32 + lane];
        float4 h1 = h4[(size_t)s1 * 32 + lane];
        float4 h2 = h4[(size_t)s2 * 32 + lane];
        float4 h3 = h4[(size_t)s3 * 32 + lane];
        float c0 = __expf(lrelu(g_alpha_s[s0] + ad + ce * w0) - m) * inv_z;
        float c1 = __expf(lrelu(g_alpha_s[s1] + ad + ce * w1) - m) * inv_z;
        float c2 = __expf(lrelu(g_alpha_s[s2] + ad + ce * w2) - m) * inv_z;
        float c3 = __expf(lrelu(g_alpha_s[s3] + ad + ce * w3) - m) * inv_z;
        acc.x += c0 * h0.x + c1 * h1.x + c2 * h2.x + c3 * h3.x;
        acc.y += c0 * h0.y + c1 * h1.y + c2 * h2.y + c3 * h3.y;
        acc.z += c0 * h0.z + c1 * h1.z + c2 * h2.z + c3 * h3.z;
        acc.w += c0 * h0.w + c1 * h1.w + c2 * h2.w + c3 * h3.w;
    }
    for (; e < end; e++) {
        int s = g_csr_src[e];
        float coef = __expf(lrelu(g_alpha_s[s] + ad + ce * g_csr_ew[e]) - m) * inv_z;
        float4 hv = h4[(size_t)s * 32 + lane];
        acc.x += coef * hv.x;
        acc.y += coef * hv.y;
        acc.z += coef * hv.z;
        acc.w += coef * hv.w;
    }

    float4 b = ((const float4*)bias_l)[lane];
    float4 r;
    r.x = gelu_exact(acc.x + b.x);
    r.y = gelu_exact(acc.y + b.y);
    r.z = gelu_exact(acc.z + b.z);
    r.w = gelu_exact(acc.w + b.w);

    if (!is_final) {
        ((float4*)g_a)[(size_t)n * 32 + lane] = r;
        return;
    }

    // fused residual + LayerNorm
    float4 xv = ((const float4*)X)[(size_t)n * 32 + lane];
    float4 v = make_float4(xv.x + r.x, xv.y + r.y, xv.z + r.z, xv.w + r.w);
    float s = v.x + v.y + v.z + v.w;
    #pragma unroll
    for (int o = 16; o; o >>= 1) s += __shfl_xor_sync(0xffffffffu, s, o);
    float mu = s * (1.0f / 128.0f);
    float dx = v.x - mu, dy = v.y - mu, dz = v.z - mu, dw = v.w - mu;
    float q = dx * dx + dy * dy + dz * dz + dw * dw;
    #pragma unroll
    for (int o = 16; o; o >>= 1) q += __shfl_xor_sync(0xffffffffu, q, o);
    float var = q * (1.0f / 128.0f);
    float inv = rsqrtf(var + LN_EPS);
    float4 g = ((const float4*)gamma)[lane];
    float4 bb = ((const float4*)beta)[lane];
    float4 o4;
    o4.x = dx * inv * g.x + bb.x;
    o4.y = dy * inv * g.y + bb.y;
    o4.z = dz * inv * g.z + bb.z;
    o4.w = dw * inv * g.w + bb.w;
    ((float4*)out)[(size_t)n * 32 + lane] = o4;
}

// ---------------- launch (kernel launches only) ----------------
extern "C" void kernel_launch(void* const* d_in, const int* in_sizes, int n_in,
                              void* d_out, int out_size) {
    (void)in_sizes; (void)n_in; (void)out_size;
    const float* x     = (const float*)d_in[0];
    const void*  ei    = d_in[1];
    const float* ew    = (const float*)d_in[2];
    const float* W     = (const float*)d_in[3];
    const float* asrc  = (const float*)d_in[4];
    const float* adst  = (const float*)d_in[5];
    const float* lew   = (const float*)d_in[6];
    const float* aedge = (const float*)d_in[7];
    const float* bias  = (const float*)d_in[8];
    const float* gamma = (const float*)d_in[9];
    const float* beta  = (const float*)d_in[10];
    float*       out   = (float*)d_out;

    const int TB = 256;
    int nb_nodes = (N_NODES + TB - 1) / TB;
    int nb_edges = (N_EDGES + TB - 1) / TB;
    int nb_warp  = (N_NODES + 7) / 8;
    int nb_gemm  = (N_NODES + 127) / 128;

    // graph prep
    k_detect<<<1, 32>>>((const int*)ei);
    k_init<<<nb_nodes, TB>>>();
    k_hist<<<nb_edges, TB>>>(ei, ew);
    k_scanA<<<SCAN_NB, SCAN_B>>>();
    k_scanB<<<1, 128>>>();
    k_scanC<<<SCAN_NB, SCAN_B>>>();
    k_scatter<<<nb_edges, TB>>>(ei, ew);
    k_selfloop<<<nb_nodes, TB>>>();
    k_pre<<<2, 128>>>(lew, aedge);

    // layer 0: x -> g_a
    k_gemm<<<nb_gemm, TB>>>(x, 0, W, asrc, adst);
    k_agg<<<nb_warp, TB>>>(0, bias, 0, x, gamma, beta, out);

    // layer 1: g_a -> out (fused residual + LN)
    k_gemm<<<nb_gemm, TB>>>(x, 1, W + D * D, asrc + D, adst + D);
    k_agg<<<nb_warp, TB>>>(1, bias + D, 1, x, gamma, beta, out);
}

// round 9
// speedup vs baseline: 1.0222x; 1.0222x over previous
#include <cuda_runtime.h>
#include <math.h>

#define N_NODES 100000
#define N_EDGES 1600000
#define D 128
#define NEG_SLOPE 0.2f
#define LN_EPS 1e-5f
#define TOT_EDGES (N_EDGES + N_NODES)
#define SCAN_B 1024
#define SCAN_NB ((N_NODES + SCAN_B - 1) / SCAN_B)   // 98

typedef unsigned long long ull;

// ---------------- device scratch (static; no allocation allowed) ----------------
static __device__ int   g_is64;
static __device__ int   g_deg[N_NODES];
static __device__ float g_wsum[N_NODES];
static __device__ int   g_rowptr[N_NODES + 1];
static __device__ int   g_cursor[N_NODES];
static __device__ int   g_bsum[SCAN_NB];
static __device__ int   g_boff[SCAN_NB];
static __device__ int   g_csr_src[TOT_EDGES];
static __device__ float g_csr_ew[TOT_EDGES];
static __device__ __align__(16) float g_h[(size_t)N_NODES * D];  // transformed features
static __device__ __align__(16) float g_a[(size_t)N_NODES * D];  // layer activations
static __device__ float g_alpha_s[N_NODES];
static __device__ float g_alpha_d[N_NODES];
static __device__ float g_ce[2];

// ---------------- helpers ----------------
__device__ __forceinline__ float gelu_exact(float v) {
    return 0.5f * v * (1.0f + erff(v * 0.7071067811865475f));
}
__device__ __forceinline__ float lrelu(float v) {
    return v > 0.0f ? v : NEG_SLOPE * v;
}
__device__ __forceinline__ void edge_sd(const void* ei, int e, int& s, int& d) {
    if (g_is64) {
        const long long* p = (const long long*)ei;
        s = (int)p[e];
        d = (int)p[N_EDGES + e];
    } else {
        const int* p = (const int*)ei;
        s = p[e];
        d = p[N_EDGES + e];
    }
}
// packed f32x2 FMA (Blackwell FFMA2; only reachable via explicit PTX)
__device__ __forceinline__ ull ffma2(ull a, ull b, ull c) {
    ull d;
    asm("fma.rn.f32x2 %0, %1, %2, %3;" : "=l"(d) : "l"(a), "l"(b), "l"(c));
    return d;
}
__device__ __forceinline__ ull dup2(float v) {
    ull d;
    unsigned int u = __float_as_uint(v);
    asm("mov.b64 %0, {%1, %1};" : "=l"(d) : "r"(u));
    return d;
}
__device__ __forceinline__ void unpack2(ull v, float& lo, float& hi) {
    unsigned int a, b;
    asm("mov.b64 {%0, %1}, %2;" : "=r"(a), "=r"(b) : "l"(v));
    lo = __uint_as_float(a);
    hi = __uint_as_float(b);
}

// ---------------- dtype detection ----------------
__global__ void k_detect(const int* __restrict__ ei32) {
    int lane = threadIdx.x;
    int orv = 0;
    for (int i = lane; i < 1024; i += 32) orv |= ei32[2 * i + 1];
    #pragma unroll
    for (int o = 16; o; o >>= 1) orv |= __shfl_xor_sync(0xffffffffu, orv, o);
    if (lane == 0) g_is64 = (orv == 0) ? 1 : 0;
}

// ---------------- graph prep ----------------
__global__ void k_init() {
    int i = blockIdx.x * blockDim.x + threadIdx.x;
    if (i < N_NODES) { g_deg[i] = 0; g_wsum[i] = 0.0f; g_cursor[i] = 0; }
}

__global__ void k_hist(const void* __restrict__ ei, const float* __restrict__ ew) {
    int e = blockIdx.x * blockDim.x + threadIdx.x;
    if (e < N_EDGES) {
        int s, d;
        edge_sd(ei, e, s, d);
        atomicAdd(&g_deg[d], 1);
        atomicAdd(&g_wsum[d], ew[e]);
    }
}

// ---- 3-phase multi-block exclusive scan of (deg[i]+1) -> rowptr ----
__global__ void __launch_bounds__(SCAN_B) k_scanA() {
    __shared__ int wsum[32];
    int tid = threadIdx.x, lane = tid & 31, wid = tid >> 5;
    int i = blockIdx.x * SCAN_B + tid;
    int v = (i < N_NODES) ? (g_deg[i] + 1) : 0;
    #pragma unroll
    for (int o = 16; o; o >>= 1) v += __shfl_xor_sync(0xffffffffu, v, o);
    if (lane == 0) wsum[wid] = v;
    __syncthreads();
    if (wid == 0) {
        int w = wsum[lane];
        #pragma unroll
        for (int o = 16; o; o >>= 1) w += __shfl_xor_sync(0xffffffffu, w, o);
        if (lane == 0) g_bsum[blockIdx.x] = w;
    }
}

__global__ void k_scanB() {
    __shared__ int wsum[4];
    int tid = threadIdx.x, lane = tid & 31, wid = tid >> 5;
    int v = (tid < SCAN_NB) ? g_bsum[tid] : 0;
    int x = v;
    #pragma unroll
    for (int o = 1; o < 32; o <<= 1) {
        int y = __shfl_up_sync(0xffffffffu, x, o);
        if (lane >= o) x += y;
    }
    if (lane == 31) wsum[wid] = x;
    __syncthreads();
    int base = 0;
    for (int w = 0; w < wid; w++) base += wsum[w];
    if (tid < SCAN_NB) g_boff[tid] = base + x - v;   // exclusive
}

// phase C: rowptr + fused self-loop CSR entry (position rowptr[i]+deg, disjoint
// from scatter's [rowptr[i], rowptr[i]+deg) range, so order vs scatter is free)
__global__ void __launch_bounds__(SCAN_B) k_scanC() {
    __shared__ int wsum[32];
    int tid = threadIdx.x, lane = tid & 31, wid = tid >> 5;
    int i = blockIdx.x * SCAN_B + tid;
    int dg = (i < N_NODES) ? g_deg[i] : 0;
    int v = (i < N_NODES) ? (dg + 1) : 0;
    int x = v;
    #pragma unroll
    for (int o = 1; o < 32; o <<= 1) {
        int y = __shfl_up_sync(0xffffffffu, x, o);
        if (lane >= o) x += y;
    }
    if (lane == 31) wsum[wid] = x;
    __syncthreads();
    if (wid == 0) {
        int w = wsum[lane];
        #pragma unroll
        for (int o = 1; o < 32; o <<= 1) {
            int y = __shfl_up_sync(0xffffffffu, w, o);
            if (lane >= o) w += y;
        }
        wsum[lane] = w;
    }
    __syncthreads();
    int incl = x + (wid > 0 ? wsum[wid - 1] : 0) + g_boff[blockIdx.x];
    if (i < N_NODES) {
        g_rowptr[i + 1] = incl;
        int pos = incl - 1;                       // self-loop slot
        g_csr_src[pos] = i;
        g_csr_ew[pos] = g_wsum[i] / (float)(dg > 0 ? dg : 1);
    }
    if (i == 0) g_rowptr[0] = 0;
}

__global__ void k_scatter(const void* __restrict__ ei, const float* __restrict__ ew) {
    int e = blockIdx.x * blockDim.x + threadIdx.x;
    if (e < N_EDGES) {
        int s, d;
        edge_sd(ei, e, s, d);
        int pos = g_rowptr[d] + atomicAdd(&g_cursor[d], 1);
        g_csr_src[pos] = s;
        g_csr_ew[pos]  = ew[e];
    }
}

__global__ void k_pre(const float* __restrict__ lew, const float* __restrict__ aedge) {
    int l = blockIdx.x;
    int t = threadIdx.x;
    __shared__ float red[4];
    float p = lew[l * D + t] * aedge[l * D + t];
    #pragma unroll
    for (int o = 16; o; o >>= 1) p += __shfl_xor_sync(0xffffffffu, p, o);
    if ((t & 31) == 0) red[t >> 5] = p;
    __syncthreads();
    if (t == 0) g_ce[l] = red[0] + red[1] + red[2] + red[3];
}

// ---------------- GEMM (FFMA2, round-5 occupancy shape) + fused alpha ----------------
// g_h[N,128] = X @ W. 64 rows/block, 256 threads, micro-tile 4 rows x 8 cols
// (4 packed column-pairs). X tile stored in smem PRE-DUPLICATED as {x,x} ulls,
// so the inner loop is pure LDS + FFMA2 (no dup movs). acc = 32 regs.
#define BK 32
__global__ void __launch_bounds__(256) k_gemm(const float* __restrict__ Xin,
                                              int use_ga,
                                              const float* __restrict__ Wm,
                                              const float* __restrict__ asrc_l,
                                              const float* __restrict__ adst_l) {
    __shared__ ull   xs2[64 * BK];     // [64][32] duplicated pairs, 16 KB
    __shared__ float ws[BK * 128];     // [32][128] 16 KB
    int tid = threadIdx.x;
    int row0 = blockIdx.x * 64;
    const float* X = use_ga ? g_a : Xin;

    int cg = tid & 15;                 // owns cols cg*4..+3 and 64+cg*4..+3
    int rg = tid >> 4;                 // owns rows rg*4..+3

    ull acc[4][4];
    #pragma unroll
    for (int i = 0; i < 4; i++)
        #pragma unroll
        for (int j = 0; j < 4; j++) acc[i][j] = 0ULL;

    const float4* X4 = (const float4*)X;
    const float4* W4 = (const float4*)Wm;
    float4* ws4 = (float4*)ws;

    for (int kb = 0; kb < 128 / BK; kb++) {
        // W chunk [BK][128]: 1024 float4s, 4/thread
        #pragma unroll
        for (int j = 0; j < 4; j++) {
            int idx = tid + j * 256;
            int kk = idx >> 5;
            int c  = idx & 31;
            ws4[idx] = W4[(size_t)(kb * BK + kk) * 32 + c];
        }
        // X chunk [64][BK]: 512 float4s, 2/thread; store duplicated pairs
        #pragma unroll
        for (int j = 0; j < 2; j++) {
            int idx = tid + j * 256;           // 0..511
            int r = idx >> 3;                  // 0..63
            int c = idx & 7;                   // float4 col within chunk
            int gr = row0 + r;
            float4 v = make_float4(0.f, 0.f, 0.f, 0.f);
            if (gr < N_NODES) v = X4[(size_t)gr * 32 + kb * 8 + c];
            ull* dst = &xs2[r * BK + c * 4];
            dst[0] = dup2(v.x);
            dst[1] = dup2(v.y);
            dst[2] = dup2(v.z);
            dst[3] = dup2(v.w);
        }
        __syncthreads();

        #pragma unroll
        for (int k = 0; k < BK; k++) {
            // conflict-free: 16 lanes read contiguous 256 B per load
            ulonglong2 bLo = *(const ulonglong2*)&ws[k * 128 + cg * 4];
            ulonglong2 bHi = *(const ulonglong2*)&ws[k * 128 + 64 + cg * 4];
            #pragma unroll
            for (int i = 0; i < 4; i++) {
                ull aa = xs2[(rg * 4 + i) * BK + k];   // broadcast (2 addrs/warp)
                acc[i][0] = ffma2(aa, bLo.x, acc[i][0]);
                acc[i][1] = ffma2(aa, bLo.y, acc[i][1]);
                acc[i][2] = ffma2(aa, bHi.x, acc[i][2]);
                acc[i][3] = ffma2(aa, bHi.y, acc[i][3]);
            }
        }
        __syncthreads();
    }

    // epilogue: store H + fused alpha dots (16-lane butterfly per row group)
    float4 sLo = ((const float4*)asrc_l)[cg];
    float4 sHi = ((const float4*)asrc_l)[16 + cg];
    float4 dLo = ((const float4*)adst_l)[cg];
    float4 dHi = ((const float4*)adst_l)[16 + cg];

    #pragma unroll
    for (int i = 0; i < 4; i++) {
        int gr = row0 + rg * 4 + i;
        float v0, v1, v2, v3, v4, v5, v6, v7;
        unpack2(acc[i][0], v0, v1);
        unpack2(acc[i][1], v2, v3);
        unpack2(acc[i][2], v4, v5);
        unpack2(acc[i][3], v6, v7);

        float ss = v0 * sLo.x + v1 * sLo.y + v2 * sLo.z + v3 * sLo.w
                 + v4 * sHi.x + v5 * sHi.y + v6 * sHi.z + v7 * sHi.w;
        float dd = v0 * dLo.x + v1 * dLo.y + v2 * dLo.z + v3 * dLo.w
                 + v4 * dHi.x + v5 * dHi.y + v6 * dHi.z + v7 * dHi.w;
        #pragma unroll
        for (int o = 8; o; o >>= 1) {              // reduce within 16-lane group
            ss += __shfl_xor_sync(0xffffffffu, ss, o);
            dd += __shfl_xor_sync(0xffffffffu, dd, o);
        }

        if (gr < N_NODES) {
            float* hp = &g_h[(size_t)gr * D];
            *((float4*)(hp + cg * 4))      = make_float4(v0, v1, v2, v3);
            *((float4*)(hp + 64 + cg * 4)) = make_float4(v4, v5, v6, v7);
            if (cg == 0) { g_alpha_s[gr] = ss; g_alpha_d[gr] = dd; }
        }
    }
}

// softmax-weighted aggregation + bias + GELU; one warp per destination node.
// If is_final: fuse residual + LayerNorm and write to out; else write to g_a.
__global__ void __launch_bounds__(256) k_agg(int l, const float* __restrict__ bias_l,
                                             int is_final,
                                             const float* __restrict__ X,
                                             const float* __restrict__ gamma,
                                             const float* __restrict__ beta,
                                             float* __restrict__ out) {
    int warp = (blockIdx.x * 256 + threadIdx.x) >> 5;
    int lane = threadIdx.x & 31;
    if (warp >= N_NODES) return;
    int n = warp;
    int start = g_rowptr[n], end = g_rowptr[n + 1];
    float ad = g_alpha_d[n];
    float ce = g_ce[l];

    // pass 1: online max + sum-exp
    float m = -1e30f, z = 0.f;
    for (int e = start + lane; e < end; e += 32) {
        int s = g_csr_src[e];
        float lg = lrelu(g_alpha_s[s] + ad + ce * g_csr_ew[e]);
        if (lg > m) { z = z * __expf(m - lg) + 1.0f; m = lg; }
        else        { z += __expf(lg - m); }
    }
    #pragma unroll
    for (int o = 16; o; o >>= 1) {
        float mo = __shfl_xor_sync(0xffffffffu, m, o);
        float zo = __shfl_xor_sync(0xffffffffu, z, o);
        float mn = fmaxf(m, mo);
        z = z * __expf(m - mn) + zo * __expf(mo - mn);
        m = mn;
    }
    float inv_z = 1.0f / z;

    // pass 2: 4-way unrolled warp-wide float4 gather
    float4 acc = make_float4(0.f, 0.f, 0.f, 0.f);
    const float4* h4 = (const float4*)g_h;
    int e = start;
    for (; e + 4 <= end; e += 4) {
        int s0 = g_csr_src[e],     s1 = g_csr_src[e + 1];
        int s2 = g_csr_src[e + 2], s3 = g_csr_src[e + 3];
        float w0 = g_csr_ew[e],     w1 = g_csr_ew[e + 1];
        float w2 = g_csr_ew[e + 2], w3 = g_csr_ew[e + 3];
        float4 h0 = h4[(size_t)s0 * 32 + lane];
        float4 h1 = h4[(size_t)s1 * 32 + lane];
        float4 h2 = h4[(size_t)s2 * 32 + lane];
        float4 h3 = h4[(size_t)s3 * 32 + lane];
        float c0 = __expf(lrelu(g_alpha_s[s0] + ad + ce * w0) - m) * inv_z;
        float c1 = __expf(lrelu(g_alpha_s[s1] + ad + ce * w1) - m) * inv_z;
        float c2 = __expf(lrelu(g_alpha_s[s2] + ad + ce * w2) - m) * inv_z;
        float c3 = __expf(lrelu(g_alpha_s[s3] + ad + ce * w3) - m) * inv_z;
        acc.x += c0 * h0.x + c1 * h1.x + c2 * h2.x + c3 * h3.x;
        acc.y += c0 * h0.y + c1 * h1.y + c2 * h2.y + c3 * h3.y;
        acc.z += c0 * h0.z + c1 * h1.z + c2 * h2.z + c3 * h3.z;
        acc.w += c0 * h0.w + c1 * h1.w + c2 * h2.w + c3 * h3.w;
    }
    for (; e < end; e++) {
        int s = g_csr_src[e];
        float coef = __expf(lrelu(g_alpha_s[s] + ad + ce * g_csr_ew[e]) - m) * inv_z;
        float4 hv = h4[(size_t)s * 32 + lane];
        acc.x += coef * hv.x;
        acc.y += coef * hv.y;
        acc.z += coef * hv.z;
        acc.w += coef * hv.w;
    }

    float4 b = ((const float4*)bias_l)[lane];
    float4 r;
    r.x = gelu_exact(acc.x + b.x);
    r.y = gelu_exact(acc.y + b.y);
    r.z = gelu_exact(acc.z + b.z);
    r.w = gelu_exact(acc.w + b.w);

    if (!is_final) {
        ((float4*)g_a)[(size_t)n * 32 + lane] = r;
        return;
    }

    // fused residual + LayerNorm
    float4 xv = ((const float4*)X)[(size_t)n * 32 + lane];
    float4 v = make_float4(xv.x + r.x, xv.y + r.y, xv.z + r.z, xv.w + r.w);
    float s = v.x + v.y + v.z + v.w;
    #pragma unroll
    for (int o = 16; o; o >>= 1) s += __shfl_xor_sync(0xffffffffu, s, o);
    float mu = s * (1.0f / 128.0f);
    float dx = v.x - mu, dy = v.y - mu, dz = v.z - mu, dw = v.w - mu;
    float q = dx * dx + dy * dy + dz * dz + dw * dw;
    #pragma unroll
    for (int o = 16; o; o >>= 1) q += __shfl_xor_sync(0xffffffffu, q, o);
    float var = q * (1.0f / 128.0f);
    float inv = rsqrtf(var + LN_EPS);
    float4 g = ((const float4*)gamma)[lane];
    float4 bb = ((const float4*)beta)[lane];
    float4 o4;
    o4.x = dx * inv * g.x + bb.x;
    o4.y = dy * inv * g.y + bb.y;
    o4.z = dz * inv * g.z + bb.z;
    o4.w = dw * inv * g.w + bb.w;
    ((float4*)out)[(size_t)n * 32 + lane] = o4;
}

// ---------------- launch (kernel launches only) ----------------
extern "C" void kernel_launch(void* const* d_in, const int* in_sizes, int n_in,
                              void* d_out, int out_size) {
    (void)in_sizes; (void)n_in; (void)out_size;
    const float* x     = (const float*)d_in[0];
    const void*  ei    = d_in[1];
    const float* ew    = (const float*)d_in[2];
    const float* W     = (const float*)d_in[3];
    const float* asrc  = (const float*)d_in[4];
    const float* adst  = (const float*)d_in[5];
    const float* lew   = (const float*)d_in[6];
    const float* aedge = (const float*)d_in[7];
    const float* bias  = (const float*)d_in[8];
    const float* gamma = (const float*)d_in[9];
    const float* beta  = (const float*)d_in[10];
    float*       out   = (float*)d_out;

    const int TB = 256;
    int nb_nodes = (N_NODES + TB - 1) / TB;
    int nb_edges = (N_EDGES + TB - 1) / TB;
    int nb_warp  = (N_NODES + 7) / 8;
    int nb_gemm  = (N_NODES + 63) / 64;

    // graph prep
    k_detect<<<1, 32>>>((const int*)ei);
    k_init<<<nb_nodes, TB>>>();
    k_hist<<<nb_edges, TB>>>(ei, ew);
    k_scanA<<<SCAN_NB, SCAN_B>>>();
    k_scanB<<<1, 128>>>();
    k_scanC<<<SCAN_NB, SCAN_B>>>();   // + fused self-loop
    k_scatter<<<nb_edges, TB>>>(ei, ew);
    k_pre<<<2, 128>>>(lew, aedge);

    // layer 0: x -> g_a
    k_gemm<<<nb_gemm, TB>>>(x, 0, W, asrc, adst);
    k_agg<<<nb_warp, TB>>>(0, bias, 0, x, gamma, beta, out);

    // layer 1: g_a -> out (fused residual + LN)
    k_gemm<<<nb_gemm, TB>>>(x, 1, W + D * D, asrc + D, adst + D);
    k_agg<<<nb_warp, TB>>>(1, bias + D, 1, x, gamma, beta, out);
}

// round 11
// speedup vs baseline: 1.1444x; 1.1195x over previous
#include <cuda_runtime.h>
#include <math.h>
#include <stdint.h>

#define N_NODES 100000
#define N_EDGES 1600000
#define D 128
#define NEG_SLOPE 0.2f
#define LN_EPS 1e-5f
#define TOT_EDGES (N_EDGES + N_NODES)
#define SCAN_B 1024
#define SCAN_NB ((N_NODES + SCAN_B - 1) / SCAN_B)   // 98

// ---------------- device scratch (static; no allocation allowed) ----------------
static __device__ int   g_is64;
static __device__ int   g_deg[N_NODES];
static __device__ float g_wsum[N_NODES];
static __device__ int   g_rowptr[N_NODES + 1];
static __device__ int   g_cursor[N_NODES];
static __device__ int   g_bsum[SCAN_NB];
static __device__ int   g_boff[SCAN_NB];
static __device__ int   g_csr_src[TOT_EDGES];
static __device__ float g_csr_ew[TOT_EDGES];
static __device__ __align__(16) float g_h[(size_t)N_NODES * D];  // transformed features
static __device__ __align__(16) float g_a[(size_t)N_NODES * D];  // layer activations
static __device__ float g_alpha_s[N_NODES];
static __device__ float g_alpha_d[N_NODES];
static __device__ float g_ce[2];

// ---------------- helpers ----------------
__device__ __forceinline__ float gelu_exact(float v) {
    return 0.5f * v * (1.0f + erff(v * 0.7071067811865475f));
}
__device__ __forceinline__ float lrelu(float v) {
    return v > 0.0f ? v : NEG_SLOPE * v;
}
__device__ __forceinline__ void edge_sd(const void* ei, int e, int& s, int& d) {
    if (g_is64) {
        const long long* p = (const long long*)ei;
        s = (int)p[e];
        d = (int)p[N_EDGES + e];
    } else {
        const int* p = (const int*)ei;
        s = p[e];
        d = p[N_EDGES + e];
    }
}
// round f32 -> tf32 (result keeps f32 bit layout, low mantissa bits zeroed)
__device__ __forceinline__ float f2tf32(float v) {
    uint32_t r;
    asm("cvt.rna.tf32.f32 %0, %1;" : "=r"(r) : "f"(v));
    return __uint_as_float(r);
}
// m16n8k8 tf32 MMA: D(16x8,f32) += A(16x8) * B(8x8)
__device__ __forceinline__ void mma_tf32(float* c, float a0, float a1, float a2, float a3,
                                         float b0, float b1) {
    asm("mma.sync.aligned.m16n8k8.row.col.f32.tf32.tf32.f32 "
        "{%0,%1,%2,%3}, {%4,%5,%6,%7}, {%8,%9}, {%0,%1,%2,%3};"
        : "+f"(c[0]), "+f"(c[1]), "+f"(c[2]), "+f"(c[3])
        : "r"(__float_as_uint(a0)), "r"(__float_as_uint(a1)),
          "r"(__float_as_uint(a2)), "r"(__float_as_uint(a3)),
          "r"(__float_as_uint(b0)), "r"(__float_as_uint(b1)));
}

// ---------------- dtype detection ----------------
__global__ void k_detect(const int* __restrict__ ei32) {
    int lane = threadIdx.x;
    int orv = 0;
    for (int i = lane; i < 1024; i += 32) orv |= ei32[2 * i + 1];
    #pragma unroll
    for (int o = 16; o; o >>= 1) orv |= __shfl_xor_sync(0xffffffffu, orv, o);
    if (lane == 0) g_is64 = (orv == 0) ? 1 : 0;
}

// ---------------- graph prep ----------------
__global__ void k_init() {
    int i = blockIdx.x * blockDim.x + threadIdx.x;
    if (i < N_NODES) { g_deg[i] = 0; g_wsum[i] = 0.0f; g_cursor[i] = 0; }
}

__global__ void k_hist(const void* __restrict__ ei, const float* __restrict__ ew) {
    int e = blockIdx.x * blockDim.x + threadIdx.x;
    if (e < N_EDGES) {
        int s, d;
        edge_sd(ei, e, s, d);
        atomicAdd(&g_deg[d], 1);
        atomicAdd(&g_wsum[d], ew[e]);
    }
}

// ---- 3-phase multi-block exclusive scan of (deg[i]+1) -> rowptr ----
__global__ void __launch_bounds__(SCAN_B) k_scanA() {
    __shared__ int wsum[32];
    int tid = threadIdx.x, lane = tid & 31, wid = tid >> 5;
    int i = blockIdx.x * SCAN_B + tid;
    int v = (i < N_NODES) ? (g_deg[i] + 1) : 0;
    #pragma unroll
    for (int o = 16; o; o >>= 1) v += __shfl_xor_sync(0xffffffffu, v, o);
    if (lane == 0) wsum[wid] = v;
    __syncthreads();
    if (wid == 0) {
        int w = wsum[lane];
        #pragma unroll
        for (int o = 16; o; o >>= 1) w += __shfl_xor_sync(0xffffffffu, w, o);
        if (lane == 0) g_bsum[blockIdx.x] = w;
    }
}

__global__ void k_scanB() {
    __shared__ int wsum[4];
    int tid = threadIdx.x, lane = tid & 31, wid = tid >> 5;
    int v = (tid < SCAN_NB) ? g_bsum[tid] : 0;
    int x = v;
    #pragma unroll
    for (int o = 1; o < 32; o <<= 1) {
        int y = __shfl_up_sync(0xffffffffu, x, o);
        if (lane >= o) x += y;
    }
    if (lane == 31) wsum[wid] = x;
    __syncthreads();
    int base = 0;
    for (int w = 0; w < wid; w++) base += wsum[w];
    if (tid < SCAN_NB) g_boff[tid] = base + x - v;   // exclusive
}

// phase C: rowptr + fused self-loop CSR entry (slot rowptr[i]+deg, disjoint
// from scatter's range, so ordering vs scatter is free)
__global__ void __launch_bounds__(SCAN_B) k_scanC() {
    __shared__ int wsum[32];
    int tid = threadIdx.x, lane = tid & 31, wid = tid >> 5;
    int i = blockIdx.x * SCAN_B + tid;
    int dg = (i < N_NODES) ? g_deg[i] : 0;
    int v = (i < N_NODES) ? (dg + 1) : 0;
    int x = v;
    #pragma unroll
    for (int o = 1; o < 32; o <<= 1) {
        int y = __shfl_up_sync(0xffffffffu, x, o);
        if (lane >= o) x += y;
    }
    if (lane == 31) wsum[wid] = x;
    __syncthreads();
    if (wid == 0) {
        int w = wsum[lane];
        #pragma unroll
        for (int o = 1; o < 32; o <<= 1) {
            int y = __shfl_up_sync(0xffffffffu, w, o);
            if (lane >= o) w += y;
        }
        wsum[lane] = w;
    }
    __syncthreads();
    int incl = x + (wid > 0 ? wsum[wid - 1] : 0) + g_boff[blockIdx.x];
    if (i < N_NODES) {
        g_rowptr[i + 1] = incl;
        int pos = incl - 1;                       // self-loop slot
        g_csr_src[pos] = i;
        g_csr_ew[pos] = g_wsum[i] / (float)(dg > 0 ? dg : 1);
    }
    if (i == 0) g_rowptr[0] = 0;
}

__global__ void k_scatter(const void* __restrict__ ei, const float* __restrict__ ew) {
    int e = blockIdx.x * blockDim.x + threadIdx.x;
    if (e < N_EDGES) {
        int s, d;
        edge_sd(ei, e, s, d);
        int pos = g_rowptr[d] + atomicAdd(&g_cursor[d], 1);
        g_csr_src[pos] = s;
        g_csr_ew[pos]  = ew[e];
    }
}

__global__ void k_pre(const float* __restrict__ lew, const float* __restrict__ aedge) {
    int l = blockIdx.x;
    int t = threadIdx.x;
    __shared__ float red[4];
    float p = lew[l * D + t] * aedge[l * D + t];
    #pragma unroll
    for (int o = 16; o; o >>= 1) p += __shfl_xor_sync(0xffffffffu, p, o);
    if ((t & 31) == 0) red[t >> 5] = p;
    __syncthreads();
    if (t == 0) g_ce[l] = red[0] + red[1] + red[2] + red[3];
}

// ---------------- GEMM: TF32 mma.sync with 3-term hi/lo split ----------------
// g_h[N,128] = X @ W, fp32-grade accuracy: D = Ah*Bh + Ah*Bl + Al*Bh.
// 256 threads (8 warps); block tile 128x128; warp tile 16 rows x 128 cols
// (16 n-tiles of m16n8k8). K chunked by 16. Fused alpha epilogue.
#define KC 16
#define XS 20                 // padded X row stride (floats): banks spread by rows
#define WS 136                // padded W row stride (floats)
__global__ void __launch_bounds__(256) k_gemm(const float* __restrict__ Xin,
                                              int use_ga,
                                              const float* __restrict__ Wm,
                                              const float* __restrict__ asrc_l,
                                              const float* __restrict__ adst_l) {
    __shared__ float xh[128 * XS], xl[128 * XS];   // 10 KB each
    __shared__ float wh[KC * WS],  wl[KC * WS];    // 8.5 KB each
    __shared__ float s_as[128], s_ad[128];
    int tid = threadIdx.x;
    int wid = tid >> 5, lane = tid & 31;
    int g = lane >> 2, tig = lane & 3;
    int row0 = blockIdx.x * 128;
    int ra = wid * 16 + g;                         // warp rows: ra, ra+8
    const float* X = use_ga ? g_a : Xin;

    if (tid < 128) { s_as[tid] = asrc_l[tid]; s_ad[tid] = adst_l[tid]; }

    float acc[16][4];
    #pragma unroll
    for (int nt = 0; nt < 16; nt++)
        #pragma unroll
        for (int j = 0; j < 4; j++) acc[nt][j] = 0.f;

    const float4* X4 = (const float4*)X;
    const float4* W4 = (const float4*)Wm;

    for (int kb = 0; kb < 128 / KC; kb++) {
        // W chunk [KC][128]: 512 float4s, 2/thread -> split hi/lo
        #pragma unroll
        for (int j = 0; j < 2; j++) {
            int idx = tid + j * 256;               // 0..511
            int kk = idx >> 5;                     // 0..15
            int c4 = idx & 31;                     // float4 col
            float4 v = W4[(size_t)(kb * KC + kk) * 32 + c4];
            float h0 = f2tf32(v.x), h1 = f2tf32(v.y), h2 = f2tf32(v.z), h3 = f2tf32(v.w);
            float* ph = &wh[kk * WS + c4 * 4];
            float* pl = &wl[kk * WS + c4 * 4];
            ph[0] = h0; ph[1] = h1; ph[2] = h2; ph[3] = h3;
            pl[0] = f2tf32(v.x - h0); pl[1] = f2tf32(v.y - h1);
            pl[2] = f2tf32(v.z - h2); pl[3] = f2tf32(v.w - h3);
        }
        // X chunk [128][KC]: 512 float4s, 2/thread -> split hi/lo
        #pragma unroll
        for (int j = 0; j < 2; j++) {
            int idx = tid + j * 256;               // 0..511
            int r  = idx >> 2;                     // 0..127
            int c4 = idx & 3;                      // 0..3
            int gr = row0 + r;
            float4 v = make_float4(0.f, 0.f, 0.f, 0.f);
            if (gr < N_NODES) v = X4[(size_t)gr * 32 + kb * 4 + c4];
            float h0 = f2tf32(v.x), h1 = f2tf32(v.y), h2 = f2tf32(v.z), h3 = f2tf32(v.w);
            float* ph = &xh[r * XS + c4 * 4];
            float* pl = &xl[r * XS + c4 * 4];
            ph[0] = h0; ph[1] = h1; ph[2] = h2; ph[3] = h3;
            pl[0] = f2tf32(v.x - h0); pl[1] = f2tf32(v.y - h1);
            pl[2] = f2tf32(v.z - h2); pl[3] = f2tf32(v.w - h3);
        }
        __syncthreads();

        #pragma unroll
        for (int ks = 0; ks < KC / 8; ks++) {
            int k0 = ks * 8;
            // A fragments (rows ra, ra+8; cols k0+tig, k0+tig+4)
            float ah0 = xh[ra * XS + k0 + tig];
            float ah1 = xh[(ra + 8) * XS + k0 + tig];
            float ah2 = xh[ra * XS + k0 + tig + 4];
            float ah3 = xh[(ra + 8) * XS + k0 + tig + 4];
            float al0 = xl[ra * XS + k0 + tig];
            float al1 = xl[(ra + 8) * XS + k0 + tig];
            float al2 = xl[ra * XS + k0 + tig + 4];
            float al3 = xl[(ra + 8) * XS + k0 + tig + 4];
            #pragma unroll
            for (int nt = 0; nt < 16; nt++) {
                int n0 = nt * 8;
                float bh0 = wh[(k0 + tig) * WS + n0 + g];
                float bh1 = wh[(k0 + tig + 4) * WS + n0 + g];
                float bl0 = wl[(k0 + tig) * WS + n0 + g];
                float bl1 = wl[(k0 + tig + 4) * WS + n0 + g];
                mma_tf32(acc[nt], ah0, ah1, ah2, ah3, bh0, bh1);
                mma_tf32(acc[nt], ah0, ah1, ah2, ah3, bl0, bl1);
                mma_tf32(acc[nt], al0, al1, al2, al3, bh0, bh1);
            }
        }
        __syncthreads();
    }

    // epilogue: H store + fused alpha dots
    int gr0 = row0 + ra, gr1 = row0 + ra + 8;
    float ss0 = 0.f, ss1 = 0.f, dd0 = 0.f, dd1 = 0.f;
    #pragma unroll
    for (int nt = 0; nt < 16; nt++) {
        int c = nt * 8 + tig * 2;
        float as0 = s_as[c], as1 = s_as[c + 1];
        float ad0 = s_ad[c], ad1 = s_ad[c + 1];
        ss0 += acc[nt][0] * as0 + acc[nt][1] * as1;
        ss1 += acc[nt][2] * as0 + acc[nt][3] * as1;
        dd0 += acc[nt][0] * ad0 + acc[nt][1] * ad1;
        dd1 += acc[nt][2] * ad0 + acc[nt][3] * ad1;
        if (gr0 < N_NODES)
            *((float2*)&g_h[(size_t)gr0 * D + c]) = make_float2(acc[nt][0], acc[nt][1]);
        if (gr1 < N_NODES)
            *((float2*)&g_h[(size_t)gr1 * D + c]) = make_float2(acc[nt][2], acc[nt][3]);
    }
    // reduce across the 4 threads of the quad (lanes g*4 .. g*4+3)
    #pragma unroll
    for (int o = 1; o < 4; o <<= 1) {
        ss0 += __shfl_xor_sync(0xffffffffu, ss0, o);
        ss1 += __shfl_xor_sync(0xffffffffu, ss1, o);
        dd0 += __shfl_xor_sync(0xffffffffu, dd0, o);
        dd1 += __shfl_xor_sync(0xffffffffu, dd1, o);
    }
    if (tig == 0) {
        if (gr0 < N_NODES) { g_alpha_s[gr0] = ss0; g_alpha_d[gr0] = dd0; }
        if (gr1 < N_NODES) { g_alpha_s[gr1] = ss1; g_alpha_d[gr1] = dd1; }
    }
}

// softmax-weighted aggregation + bias + GELU; one warp per destination node.
// If is_final: fuse residual + LayerNorm and write to out; else write to g_a.
__global__ void __launch_bounds__(256) k_agg(int l, const float* __restrict__ bias_l,
                                             int is_final,
                                             const float* __restrict__ X,
                                             const float* __restrict__ gamma,
                                             const float* __restrict__ beta,
                                             float* __restrict__ out) {
    int warp = (blockIdx.x * 256 + threadIdx.x) >> 5;
    int lane = threadIdx.x & 31;
    if (warp >= N_NODES) return;
    int n = warp;
    int start = g_rowptr[n], end = g_rowptr[n + 1];
    float ad = g_alpha_d[n];
    float ce = g_ce[l];

    // pass 1: online max + sum-exp
    float m = -1e30f, z = 0.f;
    for (int e = start + lane; e < end; e += 32) {
        int s = g_csr_src[e];
        float lg = lrelu(g_alpha_s[s] + ad + ce * g_csr_ew[e]);
        if (lg > m) { z = z * __expf(m - lg) + 1.0f; m = lg; }
        else        { z += __expf(lg - m); }
    }
    #pragma unroll
    for (int o = 16; o; o >>= 1) {
        float mo = __shfl_xor_sync(0xffffffffu, m, o);
        float zo = __shfl_xor_sync(0xffffffffu, z, o);
        float mn = fmaxf(m, mo);
        z = z * __expf(m - mn) + zo * __expf(mo - mn);
        m = mn;
    }
    float inv_z = 1.0f / z;

    // pass 2: 4-way unrolled warp-wide float4 gather
    float4 acc = make_float4(0.f, 0.f, 0.f, 0.f);
    const float4* h4 = (const float4*)g_h;
    int e = start;
    for (; e + 4 <= end; e += 4) {
        int s0 = g_csr_src[e],     s1 = g_csr_src[e + 1];
        int s2 = g_csr_src[e + 2], s3 = g_csr_src[e + 3];
        float w0 = g_csr_ew[e],     w1 = g_csr_ew[e + 1];
        float w2 = g_csr_ew[e + 2], w3 = g_csr_ew[e + 3];
        float4 h0 = h4[(size_t)s0 * 32 + lane];
        float4 h1 = h4[(size_t)s1 * 32 + lane];
        float4 h2 = h4[(size_t)s2 * 32 + lane];
        float4 h3 = h4[(size_t)s3 * 32 + lane];
        float c0 = __expf(lrelu(g_alpha_s[s0] + ad + ce * w0) - m) * inv_z;
        float c1 = __expf(lrelu(g_alpha_s[s1] + ad + ce * w1) - m) * inv_z;
        float c2 = __expf(lrelu(g_alpha_s[s2] + ad + ce * w2) - m) * inv_z;
        float c3 = __expf(lrelu(g_alpha_s[s3] + ad + ce * w3) - m) * inv_z;
        acc.x += c0 * h0.x + c1 * h1.x + c2 * h2.x + c3 * h3.x;
        acc.y += c0 * h0.y + c1 * h1.y + c2 * h2.y + c3 * h3.y;
        acc.z += c0 * h0.z + c1 * h1.z + c2 * h2.z + c3 * h3.z;
        acc.w += c0 * h0.w + c1 * h1.w + c2 * h2.w + c3 * h3.w;
    }
    for (; e < end; e++) {
        int s = g_csr_src[e];
        float coef = __expf(lrelu(g_alpha_s[s] + ad + ce * g_csr_ew[e]) - m) * inv_z;
        float4 hv = h4[(size_t)s * 32 + lane];
        acc.x += coef * hv.x;
        acc.y += coef * hv.y;
        acc.z += coef * hv.z;
        acc.w += coef * hv.w;
    }

    float4 b = ((const float4*)bias_l)[lane];
    float4 r;
    r.x = gelu_exact(acc.x + b.x);
    r.y = gelu_exact(acc.y + b.y);
    r.z = gelu_exact(acc.z + b.z);
    r.w = gelu_exact(acc.w + b.w);

    if (!is_final) {
        ((float4*)g_a)[(size_t)n * 32 + lane] = r;
        return;
    }

    // fused residual + LayerNorm
    float4 xv = ((const float4*)X)[(size_t)n * 32 + lane];
    float4 v = make_float4(xv.x + r.x, xv.y + r.y, xv.z + r.z, xv.w + r.w);
    float s = v.x + v.y + v.z + v.w;
    #pragma unroll
    for (int o = 16; o; o >>= 1) s += __shfl_xor_sync(0xffffffffu, s, o);
    float mu = s * (1.0f / 128.0f);
    float dx = v.x - mu, dy = v.y - mu, dz = v.z - mu, dw = v.w - mu;
    float q = dx * dx + dy * dy + dz * dz + dw * dw;
    #pragma unroll
    for (int o = 16; o; o >>= 1) q += __shfl_xor_sync(0xffffffffu, q, o);
    float var = q * (1.0f / 128.0f);
    float inv = rsqrtf(var + LN_EPS);
    float4 g = ((const float4*)gamma)[lane];
    float4 bb = ((const float4*)beta)[lane];
    float4 o4;
    o4.x = dx * inv * g.x + bb.x;
    o4.y = dy * inv * g.y + bb.y;
    o4.z = dz * inv * g.z + bb.z;
    o4.w = dw * inv * g.w + bb.w;
    ((float4*)out)[(size_t)n * 32 + lane] = o4;
}

// ---------------- launch (kernel launches only) ----------------
extern "C" void kernel_launch(void* const* d_in, const int* in_sizes, int n_in,
                              void* d_out, int out_size) {
    (void)in_sizes; (void)n_in; (void)out_size;
    const float* x     = (const float*)d_in[0];
    const void*  ei    = d_in[1];
    const float* ew    = (const float*)d_in[2];
    const float* W     = (const float*)d_in[3];
    const float* asrc  = (const float*)d_in[4];
    const float* adst  = (const float*)d_in[5];
    const float* lew   = (const float*)d_in[6];
    const float* aedge = (const float*)d_in[7];
    const float* bias  = (const float*)d_in[8];
    const float* gamma = (const float*)d_in[9];
    const float* beta  = (const float*)d_in[10];
    float*       out   = (float*)d_out;

    const int TB = 256;
    int nb_nodes = (N_NODES + TB - 1) / TB;
    int nb_edges = (N_EDGES + TB - 1) / TB;
    int nb_warp  = (N_NODES + 7) / 8;
    int nb_gemm  = (N_NODES + 127) / 128;

    // graph prep
    k_detect<<<1, 32>>>((const int*)ei);
    k_init<<<nb_nodes, TB>>>();
    k_hist<<<nb_edges, TB>>>(ei, ew);
    k_scanA<<<SCAN_NB, SCAN_B>>>();
    k_scanB<<<1, 128>>>();
    k_scanC<<<SCAN_NB, SCAN_B>>>();   // + fused self-loop
    k_scatter<<<nb_edges, TB>>>(ei, ew);
    k_pre<<<2, 128>>>(lew, aedge);

    // layer 0: x -> g_a
    k_gemm<<<nb_gemm, TB>>>(x, 0, W, asrc, adst);
    k_agg<<<nb_warp, TB>>>(0, bias, 0, x, gamma, beta, out);

    // layer 1: g_a -> out (fused residual + LN)
    k_gemm<<<nb_gemm, TB>>>(x, 1, W + D * D, asrc + D, adst + D);
    k_agg<<<nb_warp, TB>>>(1, bias + D, 1, x, gamma, beta, out);
}